// round 12
// baseline (speedup 1.0000x reference)
#include <cuda_runtime.h>
#include <math.h>

// ChfLoss: B=8, H=W=64, P=60. loss = (0.1/B) * sum_b ||CHF(dnn_b - gt_b)||_2
// Separable trig. ONE kernel, 120 blocks (1/SM). Epilogue: warp partials go
// to per-batch u64 FIXED-POINT global RED.ADD (order-independent => exact
// determinism), killing the g_part store/reload round-trip and 2 barriers.

#define NB      8
#define HWD     64
#define PP      60
#define PTILES  15                  // 60 / 4 p-rows per block
#define NBLK    (NB * PTILES)       // 120
#define NT      256
#define FXSCALE 1048576.0           // 2^20 fixed-point scale

// __device__ globals = sanctioned scratch (no allocation allowed)
__device__ unsigned long long g_sum[NB] = {0};  // fixed-point per-batch sums
__device__ unsigned           g_count  = 0;     // completion counter (self-reset)

// Shared: D 4096 + CS 7680 + A 512 = 12288 floats = 48KB dynamic exactly.
// NO static __shared__ anywhere (would exceed the 48KB default limit).
__global__ __launch_bounds__(NT) void chf_fused_kernel(const float* __restrict__ dnn,
                                                       const float* __restrict__ gt,
                                                       float* __restrict__ out) {
    extern __shared__ float sm[];
    float*  sD  = sm;                               // [j*64 + i]
    float2* sCS = (float2*)(sm + 4096);             // [i*60 + q] (also [j*60 + p])
    float2* sA  = (float2*)(sm + 4096 + 7680);      // [i*4 + pl] = (Ac, As)

    const int blk = blockIdx.x;
    const int b   = blk / PTILES;
    const int pt  = blk - b * PTILES;
    const int p0  = pt * 4;
    const int t   = threadIdx.x;

    // ---- issue global loads FIRST (latency hidden by table gen below) ----
    const float4* d4 = (const float4*)(dnn + b * 4096);
    const float4* g4 = (const float4*)(gt  + b * 4096);
    float4 va[4], vg[4];
    #pragma unroll
    for (int k = 0; k < 4; k++) {                    // 4*256 = 1024 float4 = ALL of D
        va[k] = d4[t + k * NT];
        vg[k] = g4[t + k * NT];
    }

    // ---- full trig table, block-private, 15 entries/thread ----
    // Ref: angle = fl(r_q * x_i) fp32, then cos/sin. Exact fp32 Cody-Waite:
    // k = rint(a/2pi) (|k|<=243 exact); fma(-k, 6.28125f, a) EXACT (both
    // multiples of 2^-13, |diff|<=3.6); 2nd fma adds ~3e-7 rad. __sincosf on
    // |ar|<=pi: ~5e-7 abs. Loss rel_err ~1e-7 << 1e-3. (R7-proven.)
    {
        const float inv2pi = 0.15915494309189535f;
        const float C1 = 6.28125f;                   // 201/32, exact
        const float C2 = 1.9353071795864769e-3f;     // 2*pi - C1
        #pragma unroll
        for (int k = 0; k < 15; k++) {
            int e = t + k * NT;                      // 0..3839 = i*60 + q
            int i = e / 60;
            int q = e - i * 60;
            float r  = (float)(q - 30) * 0.1f;       // fp32 grid, matches ref
            float x  = (float)(4 + 8 * i);           // linspace(4,508,64), exact
            float a  = r * x;                        // ref's fp32 angle
            float kk = rintf(a * inv2pi);
            float ar = fmaf(-kk, C1, a);             // exact
            ar       = fmaf(-kk, C2, ar);            // |ar| <= pi (+eps)
            float s, c;
            __sincosf(ar, &s, &c);
            sCS[e] = make_float2(c, s);              // consecutive -> conflict-free
        }
    }

    // ---- D = dnn - gt into shared ----
    {
        float4* sD4 = (float4*)sD;
        #pragma unroll
        for (int k = 0; k < 4; k++) {
            sD4[t + k * NT] = make_float4(va[k].x - vg[k].x, va[k].y - vg[k].y,
                                          va[k].z - vg[k].z, va[k].w - vg[k].w);
        }
    }
    __syncthreads();                                 // sync #1

    // ---- stage 1: t = pl*64 + ip*2 + jh -> 2 outputs (i = 2ip, 2ip+1) ----
    {
        const int jh = t & 1;                        // j half
        const int ip = (t >> 1) & 31;                // i pair
        const int pl = t >> 6;
        const int p  = p0 + pl;
        const int j0 = jh * 32;
        const float2* sD2 = (const float2*)sD;       // [j*32 + ip]
        float ac0 = 0.f, ac1 = 0.f, as0 = 0.f, as1 = 0.f;
        #pragma unroll 16
        for (int jj = 0; jj < 32; jj++) {
            int j = j0 + jj;
            float2 d  = sD2[j * 32 + ip];
            float2 cs = sCS[j * PP + p];             // broadcast (p uniform/warp)
            ac0 = fmaf(cs.x, d.x, ac0);
            ac1 = fmaf(cs.x, d.y, ac1);
            as0 = fmaf(cs.y, d.x, as0);
            as1 = fmaf(cs.y, d.y, as1);
        }
        // combine j halves with partner lane (t^1): exact & deterministic
        ac0 += __shfl_xor_sync(0xFFFFFFFFu, ac0, 1);
        ac1 += __shfl_xor_sync(0xFFFFFFFFu, ac1, 1);
        as0 += __shfl_xor_sync(0xFFFFFFFFu, as0, 1);
        as1 += __shfl_xor_sync(0xFFFFFFFFu, as1, 1);
        if (!jh) {
            sA[(2 * ip + 0) * 4 + pl] = make_float2(ac0, as0);
            sA[(2 * ip + 1) * 4 + pl] = make_float2(ac1, as1);
        }
    }
    __syncthreads();                                 // sync #2

    // ---- stage 2: t<240: t = q2*8 + pl*2 + ih -> 2 outputs (q = 2q2, 2q2+1) ----
    float v = 0.f;
    {
        const int ih = t & 1;
        const int pl = (t >> 1) & 3;
        const int q2 = t >> 3;                       // 0..29 valid (t<240)
        float r0a = 0.f, r0b = 0.f, i0a = 0.f, i0b = 0.f;
        float r1a = 0.f, r1b = 0.f, i1a = 0.f, i1b = 0.f;
        if (q2 < 30) {
            const int istart = ih * 32;
            const float4* sCS4 = (const float4*)sCS; // [i*30 + q2] = q pair
            #pragma unroll 16
            for (int ii = 0; ii < 32; ii++) {
                int i = istart + ii;
                float2 a  = sA[i * 4 + pl];          // (Ac, As)
                float4 cs = sCS4[i * 30 + q2];       // (c_q0,s_q0,c_q1,s_q1)
                r0a = fmaf(a.x, cs.x, r0a);
                r0b = fmaf(a.y, cs.y, r0b);
                i0a = fmaf(a.y, cs.x, i0a);
                i0b = fmaf(a.x, cs.y, i0b);
                r1a = fmaf(a.x, cs.z, r1a);
                r1b = fmaf(a.y, cs.w, r1b);
                i1a = fmaf(a.y, cs.z, i1a);
                i1b = fmaf(a.x, cs.w, i1b);
            }
        }
        float re0 = r0a - r0b, im0 = i0a + i0b;
        float re1 = r1a - r1b, im1 = i1a + i1b;
        re0 += __shfl_xor_sync(0xFFFFFFFFu, re0, 1); // combine i halves (exact)
        im0 += __shfl_xor_sync(0xFFFFFFFFu, im0, 1);
        re1 += __shfl_xor_sync(0xFFFFFFFFu, re1, 1);
        im1 += __shfl_xor_sync(0xFFFFFFFFu, im1, 1);
        if (!ih && q2 < 30)
            v = fmaf(re0, re0, im0 * im0) + fmaf(re1, re1, im1 * im1);
    }

    // ---- warp reduce, then u64 fixed-point global RED (deterministic) ----
    #pragma unroll
    for (int off = 16; off > 0; off >>= 1)
        v += __shfl_down_sync(0xFFFFFFFFu, v, off);
    if ((t & 31) == 0) {
        unsigned long long fx = (unsigned long long)((double)v * FXSCALE);
        atomicAdd(&g_sum[b], fx);                    // integer add: order-free
    }
    __syncthreads();                                 // sync #3: all REDs issued

    if (t == 0) {
        __threadfence();                             // publish REDs before counter
        unsigned c = atomicAdd(&g_count, 1u);
        bool last = (c == NBLK - 1);
        if (last) g_count = 0;                       // reset for next graph replay
        sD[0] = last ? 1.f : 0.f;                    // flag in dynamic smem
    }
    __syncthreads();                                 // sync #4

    // ---- last block: deterministic finalize + scratch reset ----
    if (sD[0] != 0.f && t < 32) {
        __threadfence();                             // acquire
        float w = 0.f;
        if (t < NB) {
            unsigned long long fx = *((volatile unsigned long long*)&g_sum[t]);
            w = sqrtf((float)((double)fx * (1.0 / FXSCALE)));
            g_sum[t] = 0ull;                         // reset for next replay
        }
        #pragma unroll
        for (int off = 16; off > 0; off >>= 1)
            w += __shfl_down_sync(0xFFFFFFFFu, w, off);
        if (t == 0) out[0] = w * 0.1f / 8.0f;
    }
}

// ---------------------------------------------------------------------------
extern "C" void kernel_launch(void* const* d_in, const int* in_sizes, int n_in,
                              void* d_out, int out_size) {
    (void)in_sizes; (void)n_in; (void)out_size;
    const float* dnn = (const float*)d_in[0];
    const float* gt  = (const float*)d_in[1];
    float* out = (float*)d_out;

    chf_fused_kernel<<<NBLK, NT, 12288 * sizeof(float)>>>(dnn, gt, out);
}

// round 13
// speedup vs baseline: 1.0029x; 1.0029x over previous
#include <cuda_runtime.h>
#include <math.h>

// ChfLoss: B=8, H=W=64, P=60. loss = (0.1/B) * sum_b ||CHF(dnn_b - gt_b)||_2
// Separable trig. ONE kernel, 120 blocks (1/SM), block-local trig table.
// R13: epilogue reverted to single-STG + counter (R12's per-warp atomics
// serialized in L2), one barrier removed, finalize vectorized.

#define NB      8
#define HWD     64
#define PP      60
#define PTILES  15                  // 60 / 4 p-rows per block
#define NBLK    (NB * PTILES)       // 120
#define NT      256

// __device__ globals = sanctioned scratch (no allocation allowed).
// g_part padded to 16/batch: pad entries are never written -> stay 0
// (zero-initialized at module load) -> deterministic vector loads.
__device__ float    g_part[NB * 16];
__device__ unsigned g_count = 0;          // completion counter (self-reset)

// Shared: D 4096 + CS 7680 + A 512 = 12288 floats = 48KB dynamic exactly.
// NO static __shared__ anywhere (would exceed the 48KB default limit).
__global__ __launch_bounds__(NT) void chf_fused_kernel(const float* __restrict__ dnn,
                                                       const float* __restrict__ gt,
                                                       float* __restrict__ out) {
    extern __shared__ float sm[];
    float*  sD  = sm;                               // [j*64 + i]
    float2* sCS = (float2*)(sm + 4096);             // [i*60 + q] (also [j*60 + p])
    float2* sA  = (float2*)(sm + 4096 + 7680);      // [i*4 + pl] = (Ac, As)

    const int blk = blockIdx.x;
    const int b   = blk / PTILES;
    const int pt  = blk - b * PTILES;
    const int p0  = pt * 4;
    const int t   = threadIdx.x;

    // ---- issue global loads FIRST (latency hidden by table gen below) ----
    const float4* d4 = (const float4*)(dnn + b * 4096);
    const float4* g4 = (const float4*)(gt  + b * 4096);
    float4 va[4], vg[4];
    #pragma unroll
    for (int k = 0; k < 4; k++) {                    // 4*256 = 1024 float4 = ALL of D
        va[k] = d4[t + k * NT];
        vg[k] = g4[t + k * NT];
    }

    // ---- full trig table, block-private, 15 entries/thread ----
    // Ref: angle = fl(r_q * x_i) fp32, then cos/sin. Exact fp32 Cody-Waite:
    // kk = rint(a/2pi) (|kk|<=243 exact); fma(-kk, 6.28125f, a) EXACT (both
    // multiples of 2^-13, |diff|<=3.6); 2nd fma adds ~3e-7 rad. __sincosf on
    // |ar|<=pi: ~5e-7 abs. Loss rel_err ~1e-7 << 1e-3. (R7-proven.)
    {
        const float inv2pi = 0.15915494309189535f;
        const float C1 = 6.28125f;                   // 201/32, exact
        const float C2 = 1.9353071795864769e-3f;     // 2*pi - C1
        // e = t + k*256 = i*60 + q, tracked incrementally (no division):
        // e += 256 -> q += 16, i += 4 (+1 on q wrap)
        int i = t / 60;
        int q = t - i * 60;
        #pragma unroll
        for (int k = 0; k < 15; k++) {
            float r  = (float)(q - 30) * 0.1f;       // fp32 grid, matches ref
            float x  = (float)(4 + 8 * i);           // linspace(4,508,64), exact
            float a  = r * x;                        // ref's fp32 angle
            float kk = rintf(a * inv2pi);
            float ar = fmaf(-kk, C1, a);             // exact
            ar       = fmaf(-kk, C2, ar);            // |ar| <= pi (+eps)
            float s, c;
            __sincosf(ar, &s, &c);
            sCS[i * 60 + q] = make_float2(c, s);     // e consecutive -> conflict-free
            q += 16; i += 4;
            if (q >= 60) { q -= 60; i += 1; }
        }
    }

    // ---- D = dnn - gt into shared ----
    {
        float4* sD4 = (float4*)sD;
        #pragma unroll
        for (int k = 0; k < 4; k++) {
            sD4[t + k * NT] = make_float4(va[k].x - vg[k].x, va[k].y - vg[k].y,
                                          va[k].z - vg[k].z, va[k].w - vg[k].w);
        }
    }
    __syncthreads();                                 // bar 1: sD + sCS ready

    // ---- stage 1: t = pl*64 + ip*2 + jh -> 2 outputs (i = 2ip, 2ip+1) ----
    {
        const int jh = t & 1;                        // j half
        const int ip = (t >> 1) & 31;                // i pair
        const int pl = t >> 6;
        const int p  = p0 + pl;
        const int j0 = jh * 32;
        const float2* sD2 = (const float2*)sD;       // [j*32 + ip]
        float ac0 = 0.f, ac1 = 0.f, as0 = 0.f, as1 = 0.f;
        #pragma unroll 16
        for (int jj = 0; jj < 32; jj++) {
            int j = j0 + jj;
            float2 d  = sD2[j * 32 + ip];
            float2 cs = sCS[j * PP + p];             // broadcast (p uniform/warp)
            ac0 = fmaf(cs.x, d.x, ac0);
            ac1 = fmaf(cs.x, d.y, ac1);
            as0 = fmaf(cs.y, d.x, as0);
            as1 = fmaf(cs.y, d.y, as1);
        }
        // combine j halves with partner lane (t^1): exact & deterministic
        ac0 += __shfl_xor_sync(0xFFFFFFFFu, ac0, 1);
        ac1 += __shfl_xor_sync(0xFFFFFFFFu, ac1, 1);
        as0 += __shfl_xor_sync(0xFFFFFFFFu, as0, 1);
        as1 += __shfl_xor_sync(0xFFFFFFFFu, as1, 1);
        if (!jh) {
            sA[(2 * ip + 0) * 4 + pl] = make_float2(ac0, as0);
            sA[(2 * ip + 1) * 4 + pl] = make_float2(ac1, as1);
        }
    }
    __syncthreads();                                 // bar 2: sA ready

    // ---- stage 2: t<240: t = q2*8 + pl*2 + ih -> 2 outputs (q = 2q2, 2q2+1) ----
    float v = 0.f;
    {
        const int ih = t & 1;
        const int pl = (t >> 1) & 3;
        const int q2 = t >> 3;                       // 0..29 valid (t<240)
        float r0a = 0.f, r0b = 0.f, i0a = 0.f, i0b = 0.f;
        float r1a = 0.f, r1b = 0.f, i1a = 0.f, i1b = 0.f;
        if (q2 < 30) {
            const int istart = ih * 32;
            const float4* sCS4 = (const float4*)sCS; // [i*30 + q2] = q pair
            #pragma unroll 16
            for (int ii = 0; ii < 32; ii++) {
                int i = istart + ii;
                float2 a  = sA[i * 4 + pl];          // (Ac, As)
                float4 cs = sCS4[i * 30 + q2];       // (c_q0,s_q0,c_q1,s_q1)
                r0a = fmaf(a.x, cs.x, r0a);
                r0b = fmaf(a.y, cs.y, r0b);
                i0a = fmaf(a.y, cs.x, i0a);
                i0b = fmaf(a.x, cs.y, i0b);
                r1a = fmaf(a.x, cs.z, r1a);
                r1b = fmaf(a.y, cs.w, r1b);
                i1a = fmaf(a.y, cs.z, i1a);
                i1b = fmaf(a.x, cs.w, i1b);
            }
        }
        float re0 = r0a - r0b, im0 = i0a + i0b;
        float re1 = r1a - r1b, im1 = i1a + i1b;
        re0 += __shfl_xor_sync(0xFFFFFFFFu, re0, 1); // combine i halves (exact)
        im0 += __shfl_xor_sync(0xFFFFFFFFu, im0, 1);
        re1 += __shfl_xor_sync(0xFFFFFFFFu, re1, 1);
        im1 += __shfl_xor_sync(0xFFFFFFFFu, im1, 1);
        if (!ih && q2 < 30)
            v = fmaf(re0, re0, im0 * im0) + fmaf(re1, re1, im1 * im1);
    }

    // ---- block reduce: warp shfl -> sD partials (sD free: last read stage 1,
    //      already separated by bar 2 -> no extra barrier needed) ----
    #pragma unroll
    for (int off = 16; off > 0; off >>= 1)
        v += __shfl_down_sync(0xFFFFFFFFu, v, off);
    if ((t & 31) == 0) sD[t >> 5] = v;               // 8 warp partials
    __syncthreads();                                 // bar 3
    if (t == 0) {
        float s = 0.f;
        #pragma unroll
        for (int w = 0; w < 8; w++) s += sD[w];
        g_part[b * 16 + pt] = s;
        __threadfence();                             // release before counter bump
        unsigned c = atomicAdd(&g_count, 1u);
        bool last = (c == NBLK - 1);
        if (last) g_count = 0;                       // reset for next graph replay
        sD[8] = last ? 1.f : 0.f;                    // flag in dynamic smem
    }
    __syncthreads();                                 // bar 4

    // ---- last block: deterministic finalize ----
    if (sD[8] != 0.f && t < 32) {
        __threadfence();                             // acquire: all g_part visible
        float w = 0.f;
        if (t < NB) {
            const float4* gp4 = (const float4*)(g_part + t * 16);
            float s = 0.f;
            #pragma unroll
            for (int k = 0; k < 4; k++) {            // 16 values, 4..15 pad = 0
                float4 p = gp4[k];
                s += p.x + p.y + p.z + p.w;
            }
            w = sqrtf(s);
        }
        #pragma unroll
        for (int off = 4; off > 0; off >>= 1)        // 8-lane reduce: 3 shfls
            w += __shfl_down_sync(0xFFFFFFFFu, w, off);
        if (t == 0) out[0] = w * 0.1f / 8.0f;
    }
}

// ---------------------------------------------------------------------------
extern "C" void kernel_launch(void* const* d_in, const int* in_sizes, int n_in,
                              void* d_out, int out_size) {
    (void)in_sizes; (void)n_in; (void)out_size;
    const float* dnn = (const float*)d_in[0];
    const float* gt  = (const float*)d_in[1];
    float* out = (float*)d_out;

    chf_fused_kernel<<<NBLK, NT, 12288 * sizeof(float)>>>(dnn, gt, out);
}